// round 2
// baseline (speedup 1.0000x reference)
#include <cuda_runtime.h>
#include <math.h>
#include <stdint.h>

// ---------------- problem constants ----------------
#define DIM    768
#define HEADS  12
#define HD     64
#define BATCH  2
#define TT     4
#define GW     32          // grid width (W == H == 32)
#define NTOK   4096        // tokens per batch (no cls)
#define NSEQ   4097
#define SP     1025        // spatial sequence length
#define NBT    8           // BATCH * TT
#define MLPH   3072
#define MT     8192        // temporal token rows
#define MS     8200        // spatial rows (NBT * SP)
#define MO     8194        // output rows (BATCH * NSEQ)
#define NBH    96          // NBT * HEADS

// ---------------- scratch (static device; no allocations) ----------------
__device__ float g_ln [(size_t)MS * DIM];
__device__ float g_big[(size_t)MO * MLPH];        // qkv buffers / mlp hidden
__device__ float g_att[(size_t)MS * DIM];
__device__ float g_tmp[(size_t)MS * DIM];
__device__ float g_xt [(size_t)MT * DIM];
__device__ float g_sc [(size_t)NBH * SP * SP];    // attention scores (403 MB)
__device__ float g_tab[HEADS * 63 * 63];          // geometry bias table

// ---------------- small helpers ----------------
__device__ __forceinline__ float warp_sum(float v) {
    #pragma unroll
    for (int o = 16; o; o >>= 1) v += __shfl_xor_sync(0xffffffffu, v, o);
    return v;
}
__device__ __forceinline__ float warp_max(float v) {
    #pragma unroll
    for (int o = 16; o; o >>= 1) v = fmaxf(v, __shfl_xor_sync(0xffffffffu, v, o));
    return v;
}
__device__ __forceinline__ float gelu_f(float x) {
    return 0.5f * x * (1.0f + erff(x * 0.70710678118654752440f));
}

// ---------------- geometry bias table: tab[h, dh+31, dw+31] ----------------
// dx depends only on dh = i//32 - j//32, dy only on dw = i%32 - j%32.
__global__ void bias_tab_k(const float* __restrict__ wg_w,
                           const float* __restrict__ wg_b,
                           float* __restrict__ tab) {
    int idx = blockIdx.x * blockDim.x + threadIdx.x;
    if (idx >= 63 * 63) return;
    int di = idx / 63 - 31;
    int dj = idx % 63 - 31;
    const float wbox = 1.0f + 1.0f / 32.0f;
    float dx = logf(fmaxf(fabsf(((float)di / 32.0f) / wbox), 1e-3f));
    float dy = logf(fmaxf(fabsf(((float)dj / 32.0f) / wbox), 1e-3f));
    float sx[8], cx[8], sy[8], cy[8];
    #pragma unroll
    for (int k = 0; k < 8; k++) {
        float dm = exp10f(-3.0f * (float)k / 8.0f);   // 1000^(-k/8)
        sincosf(100.0f * dx * dm, &sx[k], &cx[k]);
        sincosf(100.0f * dy * dm, &sy[k], &cy[k]);
    }
    for (int h = 0; h < HEADS; h++) {
        const float* w = wg_w + h * 64;
        float acc = wg_b[h];
        #pragma unroll
        for (int k = 0; k < 8; k++) {
            acc += w[k]      * sx[k];
            acc += w[8 + k]  * sy[k];
            acc += w[32 + k] * cx[k];
            acc += w[40 + k] * cy[k];
        }
        // emb indices 16..31 are sin(0)=0; 48..63 are cos(0)=1
        #pragma unroll
        for (int k = 48; k < 64; k++) acc += w[k];
        tab[h * 3969 + idx] = logf(fmaxf(acc, 1e-6f));  // relu then clip(1e-6) == max(acc,1e-6)
    }
}

// ---------------- layernorm (block per row of 768, 256 threads) ----------------
// MODE 0: temporal  — row r in [0,8192): src = x[b*4097 + 1 + n], b=r>>12, n=r&4095
// MODE 1: spatial gather — row r in [0,8200): bt=r/1025, p=r%1025, b=bt>>2, t=bt&3;
//         p==0 -> x[b*4097], else -> xt[b*4096 + 4*(p-1)+t]
// MODE 2: plain — src = src0 + r*768
template <int MODE>
__global__ void __launch_bounds__(256) ln_k(const float* __restrict__ src0,
                                            const float* __restrict__ src1,
                                            const float* __restrict__ gam,
                                            const float* __restrict__ bet,
                                            float* __restrict__ out) {
    int r = blockIdx.x;
    const float* src;
    if (MODE == 0) {
        int b = r >> 12, n = r & 4095;
        src = src0 + ((size_t)b * NSEQ + 1 + n) * DIM;
    } else if (MODE == 1) {
        int bt = r / SP, p = r % SP;
        int b = bt >> 2, t = bt & 3;
        src = (p == 0) ? (src0 + (size_t)b * NSEQ * DIM)
                       : (src1 + ((size_t)b * NTOK + 4 * (p - 1) + t) * DIM);
    } else {
        src = src0 + (size_t)r * DIM;
    }
    int tid = threadIdx.x;
    float v[3], s = 0.f, ss = 0.f;
    #pragma unroll
    for (int e = 0; e < 3; e++) {
        float xv = src[tid + e * 256];
        v[e] = xv; s += xv; ss += xv * xv;
    }
    __shared__ float sh1[8], sh2[8], fin[2];
    float wsu = warp_sum(s), wss = warp_sum(ss);
    int wid = tid >> 5, lane = tid & 31;
    if (lane == 0) { sh1[wid] = wsu; sh2[wid] = wss; }
    __syncthreads();
    if (tid == 0) {
        float a = 0.f, b = 0.f;
        #pragma unroll
        for (int i = 0; i < 8; i++) { a += sh1[i]; b += sh2[i]; }
        fin[0] = a; fin[1] = b;
    }
    __syncthreads();
    float mean = fin[0] * (1.0f / DIM);
    float var  = fin[1] * (1.0f / DIM) - mean * mean;
    float rstd = rsqrtf(var + 1e-5f);
    float* dst = out + (size_t)r * DIM;
    #pragma unroll
    for (int e = 0; e < 3; e++) {
        int c = tid + e * 256;
        dst[c] = (v[e] - mean) * rstd * gam[c] + bet[c];
    }
}

// ---------------- generic SGEMM: C = alpha * A @ op(B) (+ epilogue) ----------------
// A: M x K row-major (lda). NT: B is N x K row-major (ldb) -> C=A@B^T.
// NN: B is K x N row-major (ldb) -> C=A@B.
// Batched over blockIdx.z with (z/12, z%12) strides for (bt, head) addressing.
// EPI: 0 none, 1 gelu, 2 geometry-bias add (extra=tab), 3 residual add (extra, ldc)
template <int BM, int BN, int BK, int TM, int TN, bool NN, int EPI>
__global__ void __launch_bounds__(256) gemm_k(
    const float* __restrict__ A, const float* __restrict__ B,
    const float* __restrict__ bias, const float* __restrict__ extra,
    float* __restrict__ C,
    int M, int N, int K, int lda, int ldb, int ldc,
    long oA1, long oA2, long oB1, long oB2, long oC1, long oC2,
    float alpha) {
    static_assert((BM / TM) * (BN / TN) == 256, "thread count");
    __shared__ float As[BK][BM];
    __shared__ float Bs[BK][BN];
    const int tid = threadIdx.x;
    const int z = blockIdx.z, zb = z / HEADS, zh = z % HEADS;
    A += (size_t)zb * oA1 + (size_t)zh * oA2;
    B += (size_t)zb * oB1 + (size_t)zh * oB2;
    C += (size_t)zb * oC1 + (size_t)zh * oC2;
    const int brow = blockIdx.y * BM, bcol = blockIdx.x * BN;
    const int tx = tid % (BN / TN), ty = tid / (BN / TN);
    const bool a_vec = ((lda & 3) == 0) && ((((uintptr_t)A) & 15) == 0);
    const bool b_vec = ((ldb & 3) == 0) && ((((uintptr_t)B) & 15) == 0);

    float acc[TM][TN];
    #pragma unroll
    for (int i = 0; i < TM; i++)
        #pragma unroll
        for (int j = 0; j < TN; j++) acc[i][j] = 0.f;

    for (int k0 = 0; k0 < K; k0 += BK) {
        // ---- load A tile (transposed into As[k][m]) ----
        constexpr int AL = (BM * BK) / (256 * 4);
        #pragma unroll
        for (int t = 0; t < AL; t++) {
            int idx = (tid + t * 256) * 4;
            int m = idx / BK, kk = idx % BK;
            int gr = brow + m, gk = k0 + kk;
            float4 v = make_float4(0.f, 0.f, 0.f, 0.f);
            if (gr < M) {
                if (a_vec && gk + 4 <= K) {
                    v = *(const float4*)(A + (size_t)gr * lda + gk);
                } else {
                    float* pv = (float*)&v;
                    #pragma unroll
                    for (int q = 0; q < 4; q++)
                        if (gk + q < K) pv[q] = A[(size_t)gr * lda + gk + q];
                }
            }
            As[kk + 0][m] = v.x; As[kk + 1][m] = v.y;
            As[kk + 2][m] = v.z; As[kk + 3][m] = v.w;
        }
        // ---- load B tile into Bs[k][n] ----
        constexpr int BL = (BN * BK) / (256 * 4);
        if (!NN) {
            #pragma unroll
            for (int t = 0; t < BL; t++) {
                int idx = (tid + t * 256) * 4;
                int n = idx / BK, kk = idx % BK;
                int gc = bcol + n, gk = k0 + kk;
                float4 v = make_float4(0.f, 0.f, 0.f, 0.f);
                if (gc < N) {
                    if (b_vec && gk + 4 <= K) {
                        v = *(const float4*)(B + (size_t)gc * ldb + gk);
                    } else {
                        float* pv = (float*)&v;
                        #pragma unroll
                        for (int q = 0; q < 4; q++)
                            if (gk + q < K) pv[q] = B[(size_t)gc * ldb + gk + q];
                    }
                }
                Bs[kk + 0][n] = v.x; Bs[kk + 1][n] = v.y;
                Bs[kk + 2][n] = v.z; Bs[kk + 3][n] = v.w;
            }
        } else {
            #pragma unroll
            for (int t = 0; t < BL; t++) {
                int idx = (tid + t * 256) * 4;
                int kk = idx / BN, n = idx % BN;
                int gc = bcol + n, gk = k0 + kk;
                float4 v = make_float4(0.f, 0.f, 0.f, 0.f);
                if (gk < K) {
                    if (b_vec && gc + 4 <= N) {
                        v = *(const float4*)(B + (size_t)gk * ldb + gc);
                    } else {
                        float* pv = (float*)&v;
                        #pragma unroll
                        for (int q = 0; q < 4; q++)
                            if (gc + q < N) pv[q] = B[(size_t)gk * ldb + gc + q];
                    }
                }
                *(float4*)&Bs[kk][n] = v;
            }
        }
        __syncthreads();
        // ---- compute ----
        #pragma unroll
        for (int kk = 0; kk < BK; kk++) {
            float a[TM], b[TN];
            #pragma unroll
            for (int i = 0; i < TM; i++) a[i] = As[kk][ty * TM + i];
            #pragma unroll
            for (int j = 0; j < TN; j++) b[j] = Bs[kk][tx * TN + j];
            #pragma unroll
            for (int i = 0; i < TM; i++)
                #pragma unroll
                for (int j = 0; j < TN; j++) acc[i][j] += a[i] * b[j];
        }
        __syncthreads();
    }
    // ---- epilogue ----
    #pragma unroll
    for (int i = 0; i < TM; i++) {
        int gr = brow + ty * TM + i;
        if (gr >= M) continue;
        #pragma unroll
        for (int j = 0; j < TN; j++) {
            int gc = bcol + tx * TN + j;
            if (gc >= N) continue;
            float c = acc[i][j] * alpha;
            if (bias) c += __ldg(&bias[gc]);
            if (EPI == 1) c = gelu_f(c);
            if (EPI == 2) {
                if (gr > 0 && gc > 0) {
                    int qi = gr - 1, kj = gc - 1;
                    int dh = (qi >> 5) - (kj >> 5) + 31;
                    int dw = (qi & 31) - (kj & 31) + 31;
                    c += __ldg(&extra[zh * 3969 + dh * 63 + dw]);
                }
            }
            if (EPI == 3) c += extra[(size_t)gr * ldc + gc];
            C[(size_t)gr * ldc + gc] = c;
        }
    }
}

// ---------------- temporal attention: seq len 4, one warp per (seq, head) ----------------
__global__ void __launch_bounds__(128) attn_temporal_k(const float* __restrict__ qkv,
                                                       float* __restrict__ out) {
    __shared__ float sh[4][3][4][68];   // [warp][q/k/v][token][dim(padded)]
    __shared__ float shp[4][4][4];      // [warp][i][j] softmax probs
    int warp = threadIdx.x >> 5, lane = threadIdx.x & 31;
    int gid = blockIdx.x * 4 + warp;    // < 24576
    int seq = gid / HEADS, h = gid % HEADS;
    const float* base = qkv + (size_t)seq * 4 * (3 * DIM) + h * HD;
    #pragma unroll
    for (int i = 0; i < 4; i++)
        #pragma unroll
        for (int j = 0; j < 3; j++) {
            sh[warp][j][i][lane]      = base[(size_t)i * (3 * DIM) + j * DIM + lane];
            sh[warp][j][i][lane + 32] = base[(size_t)i * (3 * DIM) + j * DIM + lane + 32];
        }
    __syncwarp();
    if (lane < 16) {
        int i = lane >> 2, j = lane & 3;
        float s = 0.f;
        #pragma unroll
        for (int d = 0; d < 64; d++) s += sh[warp][0][i][d] * sh[warp][1][j][d];
        s *= 0.125f;
        float m = s;
        m = fmaxf(m, __shfl_xor_sync(0x0000ffffu, m, 1));
        m = fmaxf(m, __shfl_xor_sync(0x0000ffffu, m, 2));
        float e = expf(s - m);
        float t = e;
        t += __shfl_xor_sync(0x0000ffffu, t, 1);
        t += __shfl_xor_sync(0x0000ffffu, t, 2);
        shp[warp][i][j] = e / t;
    }
    __syncwarp();
    #pragma unroll
    for (int i = 0; i < 4; i++) {
        float o0 = 0.f, o1 = 0.f;
        #pragma unroll
        for (int j = 0; j < 4; j++) {
            float p = shp[warp][i][j];
            o0 += p * sh[warp][2][j][lane];
            o1 += p * sh[warp][2][j][lane + 32];
        }
        out[((size_t)seq * 4 + i) * DIM + h * HD + lane]      = o0;
        out[((size_t)seq * 4 + i) * DIM + h * HD + lane + 32] = o1;
    }
}

// ---------------- row softmax (block per row) ----------------
__global__ void __launch_bounds__(256) softmax_k(float* __restrict__ S, int cols) {
    float* p = S + (size_t)blockIdx.x * cols;
    int tid = threadIdx.x;
    __shared__ float sh[8], fin;
    float m = -3.4e38f;
    for (int c = tid; c < cols; c += 256) m = fmaxf(m, p[c]);
    m = warp_max(m);
    int wid = tid >> 5, lane = tid & 31;
    if (lane == 0) sh[wid] = m;
    __syncthreads();
    if (tid == 0) {
        float a = sh[0];
        #pragma unroll
        for (int i = 1; i < 8; i++) a = fmaxf(a, sh[i]);
        fin = a;
    }
    __syncthreads();
    m = fin;
    float s = 0.f;
    for (int c = tid; c < cols; c += 256) {
        float e = expf(p[c] - m);
        p[c] = e; s += e;
    }
    s = warp_sum(s);
    if (lane == 0) sh[wid] = s;
    __syncthreads();
    if (tid == 0) {
        float a = 0.f;
        #pragma unroll
        for (int i = 0; i < 8; i++) a += sh[i];
        fin = a;
    }
    __syncthreads();
    float inv = 1.0f / fin;
    for (int c = tid; c < cols; c += 256) p[c] *= inv;
}

// ---------------- xt += x[:,1:]  (temporal residual) ----------------
__global__ void add_x_k(float* __restrict__ xt, const float* __restrict__ x) {
    size_t i = (size_t)blockIdx.x * blockDim.x + threadIdx.x;
    if (i >= (size_t)MT * DIM) return;
    size_t r = i / DIM, d = i % DIM;
    size_t b = r >> 12;                         // r / 4096
    xt[i] += x[(r + 1 + b) * DIM + d];          // (b*4097 + 1 + n)*768 + d
}

// ---------------- assemble xout = concat(cls, xt) + concat(cls_out, res_s) ----------------
__global__ void __launch_bounds__(256) assemble_k(const float* __restrict__ x,
                                                  const float* __restrict__ xt,
                                                  const float* __restrict__ res_s,
                                                  float* __restrict__ out) {
    int r = blockIdx.x;                 // < 8194
    int b = (r >= NSEQ) ? 1 : 0;
    int p = r - b * NSEQ;
    int tid = threadIdx.x;
    #pragma unroll
    for (int e = 0; e < 3; e++) {
        int d = tid + e * 256;
        float v;
        if (p == 0) {
            float acc = 0.f;
            #pragma unroll
            for (int t = 0; t < TT; t++)
                acc += res_s[((size_t)(b * TT + t) * SP) * DIM + d];
            v = x[(size_t)r * DIM + d] + acc * 0.25f;
        } else {
            int n = p - 1, s = n >> 2, t = n & 3;
            v = xt[((size_t)b * NTOK + n) * DIM + d]
              + res_s[((size_t)(b * TT + t) * SP + 1 + s) * DIM + d];
        }
        out[(size_t)r * DIM + d] = v;
    }
}

// ---------------- launch ----------------
extern "C" void kernel_launch(void* const* d_in, const int* in_sizes, int n_in,
                              void* d_out, int out_size) {
    (void)in_sizes; (void)n_in; (void)out_size;
    const float* x        = (const float*)d_in[0];
    const float* norm1_g  = (const float*)d_in[1];
    const float* norm1_b  = (const float*)d_in[2];
    const float* qkv_w    = (const float*)d_in[3];
    const float* proj_w   = (const float*)d_in[4];
    const float* proj_b   = (const float*)d_in[5];
    const float* wg_w     = (const float*)d_in[6];
    const float* wg_b     = (const float*)d_in[7];
    const float* tnorm1_g = (const float*)d_in[8];
    const float* tnorm1_b = (const float*)d_in[9];
    const float* tqkv_w   = (const float*)d_in[10];
    const float* tproj_w  = (const float*)d_in[11];
    const float* tproj_b  = (const float*)d_in[12];
    const float* tfc_w    = (const float*)d_in[13];
    const float* tfc_b    = (const float*)d_in[14];
    const float* norm2_g  = (const float*)d_in[15];
    const float* norm2_b  = (const float*)d_in[16];
    const float* fc1_w    = (const float*)d_in[17];
    const float* fc1_b    = (const float*)d_in[18];
    const float* fc2_w    = (const float*)d_in[19];
    const float* fc2_b    = (const float*)d_in[20];
    float* out = (float*)d_out;

    float *ln, *big, *att, *tmp, *xt, *sc, *tab;
    cudaGetSymbolAddress((void**)&ln,  g_ln);
    cudaGetSymbolAddress((void**)&big, g_big);
    cudaGetSymbolAddress((void**)&att, g_att);
    cudaGetSymbolAddress((void**)&tmp, g_tmp);
    cudaGetSymbolAddress((void**)&xt,  g_xt);
    cudaGetSymbolAddress((void**)&sc,  g_sc);
    cudaGetSymbolAddress((void**)&tab, g_tab);

    const long SPSP = (long)SP * SP;

    // geometry bias table (independent)
    bias_tab_k<<<16, 256>>>(wg_w, wg_b, tab);

    // ---- temporal branch ----
    ln_k<0><<<MT, 256>>>(x, nullptr, tnorm1_g, tnorm1_b, ln);
    gemm_k<128,128,16,8,8,false,0><<<dim3(18,64,1), 256>>>(
        ln, tqkv_w, nullptr, nullptr, big,
        MT, 3*DIM, DIM, DIM, DIM, 3*DIM, 0,0,0,0,0,0, 1.0f);
    attn_temporal_k<<<(MT/4*HEADS)/4, 128>>>(big, att);
    gemm_k<128,128,16,8,8,false,0><<<dim3(6,64,1), 256>>>(
        att, tproj_w, tproj_b, nullptr, tmp,
        MT, DIM, DIM, DIM, DIM, DIM, 0,0,0,0,0,0, 1.0f);
    gemm_k<128,128,16,8,8,false,0><<<dim3(6,64,1), 256>>>(
        tmp, tfc_w, tfc_b, nullptr, xt,
        MT, DIM, DIM, DIM, DIM, DIM, 0,0,0,0,0,0, 1.0f);
    add_x_k<<<(int)(((size_t)MT*DIM + 255)/256), 256>>>(xt, x);

    // ---- spatial branch ----
    ln_k<1><<<MS, 256>>>(x, xt, norm1_g, norm1_b, ln);
    gemm_k<128,128,16,8,8,false,0><<<dim3(18,65,1), 256>>>(
        ln, qkv_w, nullptr, nullptr, big,
        MS, 3*DIM, DIM, DIM, DIM, 3*DIM, 0,0,0,0,0,0, 1.0f);
    // scores = (Q K^T) * 0.125 + geom_bias  — batched over (bt, h)
    gemm_k<128,128,16,8,8,false,2><<<dim3(9,9,NBH), 256>>>(
        big, big + DIM, nullptr, tab, sc,
        SP, SP, HD, 3*DIM, 3*DIM, SP,
        (long)SP*3*DIM, 64L, (long)SP*3*DIM, 64L,
        (long)HEADS*SPSP, SPSP, 0.125f);
    softmax_k<<<NBH*SP, 256>>>(sc, SP);
    // out = P @ V  — batched, NN
    gemm_k<128,64,16,8,4,true,0><<<dim3(1,9,NBH), 256>>>(
        sc, big + 2*DIM, nullptr, nullptr, att,
        SP, HD, SP, SP, 3*DIM, DIM,
        (long)HEADS*SPSP, SPSP, (long)SP*3*DIM, 64L,
        (long)SP*DIM, 64L, 1.0f);
    gemm_k<128,128,16,8,8,false,0><<<dim3(6,65,1), 256>>>(
        att, proj_w, proj_b, nullptr, tmp,
        MS, DIM, DIM, DIM, DIM, DIM, 0,0,0,0,0,0, 1.0f);

    // ---- assemble xout into d_out ----
    assemble_k<<<MO, 256>>>(x, xt, tmp, out);

    // ---- MLP ----
    ln_k<2><<<MO, 256>>>(out, nullptr, norm2_g, norm2_b, ln);
    gemm_k<128,128,16,8,8,false,1><<<dim3(24,65,1), 256>>>(
        ln, fc1_w, fc1_b, nullptr, big,
        MO, MLPH, DIM, DIM, DIM, MLPH, 0,0,0,0,0,0, 1.0f);
    gemm_k<128,128,16,8,8,false,3><<<dim3(6,65,1), 256>>>(
        big, fc2_w, fc2_b, out, out,
        MO, DIM, MLPH, MLPH, MLPH, DIM, 0,0,0,0,0,0, 1.0f);
}

// round 7
// speedup vs baseline: 2.0615x; 2.0615x over previous
#include <cuda_runtime.h>
#include <cuda_bf16.h>
#include <math.h>
#include <stdint.h>

// ---------------- problem constants ----------------
#define DIM    768
#define HEADS  12
#define HD     64
#define TT     4
#define NTOK   4096
#define NSEQ   4097
#define SP     1025
#define MLPH   3072
#define MT     8192
#define MS     8200
#define MO     8194
#define NBH    96

// ---------------- scratch (static device; no allocations) ----------------
__device__ float g_big[(size_t)MO * MLPH];       // qkv outputs (fp32)
__device__ float g_tmp[(size_t)MS * DIM];
__device__ float g_xt [(size_t)MT * DIM];
__device__ float g_sc [(size_t)NBH * SP * SP];
__device__ float g_tab[HEADS * 63 * 63];
// bf16 hi/lo planes (uint4 for 16B alignment)
__device__ uint4 g_wh4 [1253376], g_wl4 [1253376];   // all weights, concatenated
__device__ uint4 g_lnh4[787200],  g_lnl4[787200];    // layernorm out (MS x DIM)
__device__ uint4 g_ath4[787200],  g_atl4[787200];    // attention out (MS x DIM)
__device__ uint4 g_tph4[786432],  g_tpl4[786432];    // tproj out (MT x DIM)
__device__ uint4 g_bgh4[3146496], g_bgl4[3146496];   // fc1 out (MO x MLPH)

// weight plane offsets (elements)
#define OFF_TQKV 0
#define OFF_TPROJ 1769472
#define OFF_TFC  2359296
#define OFF_QKV  2949120
#define OFF_PROJ 4718592
#define OFF_FC1  5308416
#define OFF_FC2  7667712

// ---------------- helpers ----------------
__device__ __forceinline__ uint32_t smem_u32(const void* p) {
    uint32_t a;
    asm("{ .reg .u64 t; cvta.to.shared.u64 t, %1; cvt.u32.u64 %0, t; }" : "=r"(a) : "l"(p));
    return a;
}
__device__ __forceinline__ float warp_sum(float v) {
    #pragma unroll
    for (int o = 16; o; o >>= 1) v += __shfl_xor_sync(0xffffffffu, v, o);
    return v;
}
__device__ __forceinline__ float warp_max(float v) {
    #pragma unroll
    for (int o = 16; o; o >>= 1) v = fmaxf(v, __shfl_xor_sync(0xffffffffu, v, o));
    return v;
}
__device__ __forceinline__ float gelu_f(float x) {
    return 0.5f * x * (1.0f + erff(x * 0.70710678118654752440f));
}
__device__ __forceinline__ void split_bf16(float v, __nv_bfloat16& h, __nv_bfloat16& l) {
    h = __float2bfloat16(v);
    l = __float2bfloat16(v - __bfloat162float(h));
}

// ---------------- weight fp32 -> bf16 hi/lo ----------------
__global__ void cvt_k(const float* __restrict__ src, __nv_bfloat16* __restrict__ h,
                      __nv_bfloat16* __restrict__ l, int n) {
    int i = blockIdx.x * 256 + threadIdx.x;
    if (i < n) {
        __nv_bfloat16 hh, ll;
        split_bf16(src[i], hh, ll);
        h[i] = hh; l[i] = ll;
    }
}

// ---------------- geometry bias table ----------------
__global__ void bias_tab_k(const float* __restrict__ wg_w,
                           const float* __restrict__ wg_b,
                           float* __restrict__ tab) {
    int idx = blockIdx.x * blockDim.x + threadIdx.x;
    if (idx >= 63 * 63) return;
    int di = idx / 63 - 31;
    int dj = idx % 63 - 31;
    const float wbox = 1.0f + 1.0f / 32.0f;
    float dx = logf(fmaxf(fabsf(((float)di / 32.0f) / wbox), 1e-3f));
    float dy = logf(fmaxf(fabsf(((float)dj / 32.0f) / wbox), 1e-3f));
    float sx[8], cx[8], sy[8], cy[8];
    #pragma unroll
    for (int k = 0; k < 8; k++) {
        float dm = exp10f(-3.0f * (float)k / 8.0f);
        sincosf(100.0f * dx * dm, &sx[k], &cx[k]);
        sincosf(100.0f * dy * dm, &sy[k], &cy[k]);
    }
    for (int h = 0; h < HEADS; h++) {
        const float* w = wg_w + h * 64;
        float acc = wg_b[h];
        #pragma unroll
        for (int k = 0; k < 8; k++) {
            acc += w[k] * sx[k];
            acc += w[8 + k] * sy[k];
            acc += w[32 + k] * cx[k];
            acc += w[40 + k] * cy[k];
        }
        #pragma unroll
        for (int k = 48; k < 64; k++) acc += w[k];
        tab[h * 3969 + idx] = logf(fmaxf(acc, 1e-6f));
    }
}

// ---------------- layernorm -> bf16 hi/lo planes ----------------
template <int MODE>
__global__ void __launch_bounds__(256) ln_k(const float* __restrict__ src0,
                                            const float* __restrict__ src1,
                                            const float* __restrict__ gam,
                                            const float* __restrict__ bet,
                                            __nv_bfloat16* __restrict__ oh,
                                            __nv_bfloat16* __restrict__ ol) {
    int r = blockIdx.x;
    const float* src;
    if (MODE == 0) {
        int b = r >> 12, n = r & 4095;
        src = src0 + ((size_t)b * NSEQ + 1 + n) * DIM;
    } else if (MODE == 1) {
        int bt = r / SP, p = r % SP;
        int b = bt >> 2, t = bt & 3;
        src = (p == 0) ? (src0 + (size_t)b * NSEQ * DIM)
                       : (src1 + ((size_t)b * NTOK + 4 * (p - 1) + t) * DIM);
    } else {
        src = src0 + (size_t)r * DIM;
    }
    int tid = threadIdx.x;
    float v[3], s = 0.f, ss = 0.f;
    #pragma unroll
    for (int e = 0; e < 3; e++) {
        float xv = src[tid + e * 256];
        v[e] = xv; s += xv; ss += xv * xv;
    }
    __shared__ float sh1[8], sh2[8], fin[2];
    float wsu = warp_sum(s), wss = warp_sum(ss);
    int wid = tid >> 5, lane = tid & 31;
    if (lane == 0) { sh1[wid] = wsu; sh2[wid] = wss; }
    __syncthreads();
    if (tid == 0) {
        float a = 0.f, b = 0.f;
        #pragma unroll
        for (int i = 0; i < 8; i++) { a += sh1[i]; b += sh2[i]; }
        fin[0] = a; fin[1] = b;
    }
    __syncthreads();
    float mean = fin[0] * (1.0f / DIM);
    float var  = fin[1] * (1.0f / DIM) - mean * mean;
    float rstd = rsqrtf(var + 1e-5f);
    #pragma unroll
    for (int e = 0; e < 3; e++) {
        int c = tid + e * 256;
        float y = (v[e] - mean) * rstd * gam[c] + bet[c];
        __nv_bfloat16 hh, ll;
        split_bf16(y, hh, ll);
        oh[(size_t)r * DIM + c] = hh;
        ol[(size_t)r * DIM + c] = ll;
    }
}

// ================= bf16x3 tensor-core GEMM via mma.sync =================
// C(MxN) = A(MxK) @ B(NxK)^T, A/B given as bf16 hi/lo planes (K-major, ld=K).
// 128x128 CTA tile, BK=32, 256 threads = 8 warps (2m x 4n), warp tile 64x32.
// N, K multiples of 128/32. M arbitrary (guards).
#define MM_SMEM 81920   // 2 stages * 4 planes * 128 rows * 40 elems * 2B

__device__ __forceinline__ void mma_bf16(float* d, const uint32_t* a, const uint32_t* b) {
    asm volatile(
        "mma.sync.aligned.m16n8k16.row.col.f32.bf16.bf16.f32 "
        "{%0,%1,%2,%3}, {%4,%5,%6,%7}, {%8,%9}, {%0,%1,%2,%3};"
        : "+f"(d[0]), "+f"(d[1]), "+f"(d[2]), "+f"(d[3])
        : "r"(a[0]), "r"(a[1]), "r"(a[2]), "r"(a[3]), "r"(b[0]), "r"(b[1]));
}

__device__ __forceinline__ void fill_stage(
    char* smem, int stage,
    const __nv_bfloat16* __restrict__ Ah, const __nv_bfloat16* __restrict__ Al,
    const __nv_bfloat16* __restrict__ Bh, const __nv_bfloat16* __restrict__ Bl,
    int brow, int bcol, int M, int K, int kt) {
    uint32_t sb = smem_u32(smem) + (uint32_t)stage * 40960u;
    int tid = threadIdx.x;
    const __nv_bfloat16* planes[4] = {Ah, Al, Bh, Bl};
    #pragma unroll
    for (int p = 0; p < 4; p++) {
        int rbase = (p < 2) ? brow : bcol;
        #pragma unroll
        for (int q = 0; q < 2; q++) {
            int id = tid + q * 256;
            int row = id >> 2, ch = id & 3;
            int grow = rbase + row;
            bool ok = (p >= 2) || (grow < M);
            const __nv_bfloat16* src = planes[p] +
                ((size_t)(ok ? grow : 0) * K + kt * 32 + ch * 8);
            uint32_t dst = sb + (uint32_t)p * 10240u + (uint32_t)(row * 80 + ch * 16);
            int sz = ok ? 16 : 0;
            asm volatile("cp.async.cg.shared.global [%0], [%1], 16, %2;"
                         :: "r"(dst), "l"(src), "r"(sz));
        }
    }
}

template <bool GELU, bool RES, bool OUT16>
__global__ void __launch_bounds__(256) mma_gemm_k(
    const __nv_bfloat16* __restrict__ Ah, const __nv_bfloat16* __restrict__ Al,
    const __nv_bfloat16* __restrict__ Bh, const __nv_bfloat16* __restrict__ Bl,
    const float* __restrict__ bias, const float* __restrict__ resid,
    float* __restrict__ C, __nv_bfloat16* __restrict__ Ch, __nv_bfloat16* __restrict__ Cl,
    int M, int N, int K, int ldc) {
    extern __shared__ char smem[];
    const int tid = threadIdx.x, wid = tid >> 5, lane = tid & 31;
    const int wm = wid >> 2, wn = wid & 3;
    const int brow = blockIdx.y * 128, bcol = blockIdx.x * 128;
    const int KT = K >> 5;

    float acc[4][4][4];
    #pragma unroll
    for (int i = 0; i < 4; i++)
        #pragma unroll
        for (int j = 0; j < 4; j++)
            #pragma unroll
            for (int r = 0; r < 4; r++) acc[i][j][r] = 0.f;

    fill_stage(smem, 0, Ah, Al, Bh, Bl, brow, bcol, M, K, 0);
    asm volatile("cp.async.commit_group;");

    for (int kt = 0; kt < KT; kt++) {
        if (kt + 1 < KT) {
            fill_stage(smem, (kt + 1) & 1, Ah, Al, Bh, Bl, brow, bcol, M, K, kt + 1);
            asm volatile("cp.async.commit_group;");
            asm volatile("cp.async.wait_group 1;");
        } else {
            asm volatile("cp.async.wait_group 0;");
        }
        __syncthreads();

        char* sbuf = smem + (kt & 1) * 40960;
        const __nv_bfloat16* As_h = (const __nv_bfloat16*)sbuf;
        const __nv_bfloat16* As_l = (const __nv_bfloat16*)(sbuf + 10240);
        const __nv_bfloat16* Bs_h = (const __nv_bfloat16*)(sbuf + 20480);
        const __nv_bfloat16* Bs_l = (const __nv_bfloat16*)(sbuf + 30720);

        #pragma unroll
        for (int ks = 0; ks < 2; ks++) {
            int c = ks * 16 + (lane & 3) * 2;
            uint32_t ah[4][4], al[4][4], bh[4][2], bl[4][2];
            #pragma unroll
            for (int i = 0; i < 4; i++) {
                int r = wm * 64 + i * 16 + (lane >> 2);
                const __nv_bfloat16* ph = As_h + r * 40 + c;
                const __nv_bfloat16* pl = As_l + r * 40 + c;
                ah[i][0] = *(const uint32_t*)ph;
                ah[i][1] = *(const uint32_t*)(ph + 320);
                ah[i][2] = *(const uint32_t*)(ph + 8);
                ah[i][3] = *(const uint32_t*)(ph + 328);
                al[i][0] = *(const uint32_t*)pl;
                al[i][1] = *(const uint32_t*)(pl + 320);
                al[i][2] = *(const uint32_t*)(pl + 8);
                al[i][3] = *(const uint32_t*)(pl + 328);
            }
            #pragma unroll
            for (int j = 0; j < 4; j++) {
                int r = wn * 32 + j * 8 + (lane >> 2);
                const __nv_bfloat16* ph = Bs_h + r * 40 + c;
                const __nv_bfloat16* pl = Bs_l + r * 40 + c;
                bh[j][0] = *(const uint32_t*)ph;
                bh[j][1] = *(const uint32_t*)(ph + 8);
                bl[j][0] = *(const uint32_t*)pl;
                bl[j][1] = *(const uint32_t*)(pl + 8);
            }
            #pragma unroll
            for (int i = 0; i < 4; i++)
                #pragma unroll
                for (int j = 0; j < 4; j++) {
                    mma_bf16(acc[i][j], ah[i], bh[j]);
                    mma_bf16(acc[i][j], ah[i], bl[j]);
                    mma_bf16(acc[i][j], al[i], bh[j]);
                }
        }
        __syncthreads();
    }

    // epilogue
    #pragma unroll
    for (int i = 0; i < 4; i++) {
        int r0 = brow + wm * 64 + i * 16 + (lane >> 2);
        int r1 = r0 + 8;
        #pragma unroll
        for (int j = 0; j < 4; j++) {
            int col = bcol + wn * 32 + j * 8 + (lane & 3) * 2;
            float b0 = bias ? __ldg(&bias[col]) : 0.f;
            float b1 = bias ? __ldg(&bias[col + 1]) : 0.f;
            #pragma unroll
            for (int half = 0; half < 2; half++) {
                int gr = half ? r1 : r0;
                if (gr >= M) continue;
                float v0 = acc[i][j][half * 2 + 0] + b0;
                float v1 = acc[i][j][half * 2 + 1] + b1;
                if (GELU) { v0 = gelu_f(v0); v1 = gelu_f(v1); }
                if (RES) {
                    v0 += resid[(size_t)gr * ldc + col];
                    v1 += resid[(size_t)gr * ldc + col + 1];
                }
                if (OUT16) {
                    __nv_bfloat16 h0, l0, h1, l1;
                    split_bf16(v0, h0, l0);
                    split_bf16(v1, h1, l1);
                    uint32_t hp = ((uint32_t)__bfloat16_as_ushort(h1) << 16) | __bfloat16_as_ushort(h0);
                    uint32_t lp = ((uint32_t)__bfloat16_as_ushort(l1) << 16) | __bfloat16_as_ushort(l0);
                    *(uint32_t*)(Ch + (size_t)gr * ldc + col) = hp;
                    *(uint32_t*)(Cl + (size_t)gr * ldc + col) = lp;
                } else {
                    *(float2*)(C + (size_t)gr * ldc + col) = make_float2(v0, v1);
                }
            }
        }
    }
}

// ---------------- SIMT SGEMM (scores + PV) ----------------
// EPI: 0 none, 2 geometry-bias add. PLANES: write bf16 hi/lo planes instead of fp32.
template <int BM, int BN, int BK, int TM, int TN, bool NN, int EPI, bool PLANES>
__global__ void __launch_bounds__(256) gemm_k(
    const float* __restrict__ A, const float* __restrict__ B,
    const float* __restrict__ extra, float* __restrict__ C,
    __nv_bfloat16* __restrict__ Ch, __nv_bfloat16* __restrict__ Cl,
    int M, int N, int K, int lda, int ldb, int ldc,
    long oA1, long oA2, long oB1, long oB2, long oC1, long oC2,
    float alpha) {
    static_assert((BM / TM) * (BN / TN) == 256, "thread count");
    __shared__ float As[BK][BM];
    __shared__ float Bs[BK][BN];
    const int tid = threadIdx.x;
    const int z = blockIdx.z, zb = z / HEADS, zh = z % HEADS;
    A += (size_t)zb * oA1 + (size_t)zh * oA2;
    B += (size_t)zb * oB1 + (size_t)zh * oB2;
    size_t coff = (size_t)zb * oC1 + (size_t)zh * oC2;
    const int brow = blockIdx.y * BM, bcol = blockIdx.x * BN;
    const int tx = tid % (BN / TN), ty = tid / (BN / TN);
    const bool a_vec = ((lda & 3) == 0) && ((((uintptr_t)A) & 15) == 0);
    const bool b_vec = ((ldb & 3) == 0) && ((((uintptr_t)B) & 15) == 0);

    float acc[TM][TN];
    #pragma unroll
    for (int i = 0; i < TM; i++)
        #pragma unroll
        for (int j = 0; j < TN; j++) acc[i][j] = 0.f;

    for (int k0 = 0; k0 < K; k0 += BK) {
        constexpr int AL = (BM * BK) / (256 * 4);
        #pragma unroll
        for (int t = 0; t < AL; t++) {
            int idx = (tid + t * 256) * 4;
            int m = idx / BK, kk = idx % BK;
            int gr = brow + m, gk = k0 + kk;
            float4 v = make_float4(0.f, 0.f, 0.f, 0.f);
            if (gr < M) {
                if (a_vec && gk + 4 <= K) {
                    v = *(const float4*)(A + (size_t)gr * lda + gk);
                } else {
                    float* pv = (float*)&v;
                    #pragma unroll
                    for (int q = 0; q < 4; q++)
                        if (gk + q < K) pv[q] = A[(size_t)gr * lda + gk + q];
                }
            }
            As[kk + 0][m] = v.x; As[kk + 1][m] = v.y;
            As[kk + 2][m] = v.z; As[kk + 3][m] = v.w;
        }
        constexpr int BL = (BN * BK) / (256 * 4);
        if (!NN) {
            #pragma unroll
            for (int t = 0; t < BL; t++) {
                int idx = (tid + t * 256) * 4;
                int n = idx / BK, kk = idx % BK;
                int gc = bcol + n, gk = k0 + kk;
                float4 v = make_float4(0.f, 0.f, 0.f, 0.f);
                if (gc < N) {
                    if (b_vec && gk + 4 <= K) {
                        v = *(const float4*)(B + (size_t)gc * ldb + gk);
                    } else {
                        float* pv = (float*)&v;
                        #pragma unroll
                        for (int q = 0; q < 4; q++)
                            if (gk + q < K) pv[q] = B[(size_t)gc * ldb + gk + q];
                    }
                }
                Bs[kk + 0][n] = v.x; Bs[kk + 1][n] = v.y;
                Bs[kk + 2][n] = v.z; Bs[kk + 3][n] = v.w;
            }
        } else {
            #pragma unroll
            for (int t = 0; t < BL; t++) {
                int idx = (tid + t * 256) * 4;
                int kk = idx / BN, n = idx % BN;
                int gc = bcol + n, gk = k0 + kk;
                float4 v = make_float4(0.f, 0.f, 0.f, 0.f);
                if (gk < K) {
                    if (b_vec && gc + 4 <= N) {
                        v = *(const float4*)(B + (size_t)gk * ldb + gc);
                    } else {
                        float* pv = (float*)&v;
                        #pragma unroll
                        for (int q = 0; q < 4; q++)
                            if (gc + q < N) pv[q] = B[(size_t)gk * ldb + gc + q];
                    }
                }
                *(float4*)&Bs[kk][n] = v;
            }
        }
        __syncthreads();
        #pragma unroll
        for (int kk = 0; kk < BK; kk++) {
            float a[TM], b[TN];
            #pragma unroll
            for (int i = 0; i < TM; i++) a[i] = As[kk][ty * TM + i];
            #pragma unroll
            for (int j = 0; j < TN; j++) b[j] = Bs[kk][tx * TN + j];
            #pragma unroll
            for (int i = 0; i < TM; i++)
                #pragma unroll
                for (int j = 0; j < TN; j++) acc[i][j] += a[i] * b[j];
        }
        __syncthreads();
    }
    #pragma unroll
    for (int i = 0; i < TM; i++) {
        int gr = brow + ty * TM + i;
        if (gr >= M) continue;
        #pragma unroll
        for (int j = 0; j < TN; j++) {
            int gc = bcol + tx * TN + j;
            if (gc >= N) continue;
            float c = acc[i][j] * alpha;
            if (EPI == 2) {
                if (gr > 0 && gc > 0) {
                    int qi = gr - 1, kj = gc - 1;
                    int dh = (qi >> 5) - (kj >> 5) + 31;
                    int dw = (qi & 31) - (kj & 31) + 31;
                    c += __ldg(&extra[zh * 3969 + dh * 63 + dw]);
                }
            }
            if (PLANES) {
                __nv_bfloat16 hh, ll;
                split_bf16(c, hh, ll);
                Ch[coff + (size_t)gr * ldc + gc] = hh;
                Cl[coff + (size_t)gr * ldc + gc] = ll;
            } else {
                C[coff + (size_t)gr * ldc + gc] = c;
            }
        }
    }
}

// ---------------- temporal attention (writes bf16 hi/lo planes) ----------------
__global__ void __launch_bounds__(128) attn_temporal_k(const float* __restrict__ qkv,
                                                       __nv_bfloat16* __restrict__ oh,
                                                       __nv_bfloat16* __restrict__ ol) {
    __shared__ float sh[4][3][4][68];
    __shared__ float shp[4][4][4];
    int warp = threadIdx.x >> 5, lane = threadIdx.x & 31;
    int gid = blockIdx.x * 4 + warp;
    int seq = gid / HEADS, h = gid % HEADS;
    const float* base = qkv + (size_t)seq * 4 * (3 * DIM) + h * HD;
    #pragma unroll
    for (int i = 0; i < 4; i++)
        #pragma unroll
        for (int j = 0; j < 3; j++) {
            sh[warp][j][i][lane]      = base[(size_t)i * (3 * DIM) + j * DIM + lane];
            sh[warp][j][i][lane + 32] = base[(size_t)i * (3 * DIM) + j * DIM + lane + 32];
        }
    __syncwarp();
    if (lane < 16) {
        int i = lane >> 2, j = lane & 3;
        float s = 0.f;
        #pragma unroll
        for (int d = 0; d < 64; d++) s += sh[warp][0][i][d] * sh[warp][1][j][d];
        s *= 0.125f;
        float m = s;
        m = fmaxf(m, __shfl_xor_sync(0x0000ffffu, m, 1));
        m = fmaxf(m, __shfl_xor_sync(0x0000ffffu, m, 2));
        float e = expf(s - m);
        float t = e;
        t += __shfl_xor_sync(0x0000ffffu, t, 1);
        t += __shfl_xor_sync(0x0000ffffu, t, 2);
        shp[warp][i][j] = e / t;
    }
    __syncwarp();
    #pragma unroll
    for (int i = 0; i < 4; i++) {
        float o0 = 0.f, o1 = 0.f;
        #pragma unroll
        for (int j = 0; j < 4; j++) {
            float p = shp[warp][i][j];
            o0 += p * sh[warp][2][j][lane];
            o1 += p * sh[warp][2][j][lane + 32];
        }
        size_t base_o = ((size_t)seq * 4 + i) * DIM + h * HD;
        __nv_bfloat16 hh, ll;
        split_bf16(o0, hh, ll);
        oh[base_o + lane] = hh; ol[base_o + lane] = ll;
        split_bf16(o1, hh, ll);
        oh[base_o + lane + 32] = hh; ol[base_o + lane + 32] = ll;
    }
}

// ---------------- row softmax ----------------
__global__ void __launch_bounds__(256) softmax_k(float* __restrict__ S, int cols) {
    float* p = S + (size_t)blockIdx.x * cols;
    int tid = threadIdx.x;
    __shared__ float sh[8], fin;
    float m = -3.4e38f;
    for (int c = tid; c < cols; c += 256) m = fmaxf(m, p[c]);
    m = warp_max(m);
    int wid = tid >> 5, lane = tid & 31;
    if (lane == 0) sh[wid] = m;
    __syncthreads();
    if (tid == 0) {
        float a = sh[0];
        #pragma unroll
        for (int i = 1; i < 8; i++) a = fmaxf(a, sh[i]);
        fin = a;
    }
    __syncthreads();
    m = fin;
    float s = 0.f;
    for (int c = tid; c < cols; c += 256) {
        float e = expf(p[c] - m);
        p[c] = e; s += e;
    }
    s = warp_sum(s);
    if (lane == 0) sh[wid] = s;
    __syncthreads();
    if (tid == 0) {
        float a = 0.f;
        #pragma unroll
        for (int i = 0; i < 8; i++) a += sh[i];
        fin = a;
    }
    __syncthreads();
    float inv = 1.0f / fin;
    for (int c = tid; c < cols; c += 256) p[c] *= inv;
}

// ---------------- xt += x[:,1:] ----------------
__global__ void add_x_k(float* __restrict__ xt, const float* __restrict__ x) {
    size_t i = (size_t)blockIdx.x * blockDim.x + threadIdx.x;
    if (i >= (size_t)MT * DIM) return;
    size_t r = i / DIM, d = i % DIM;
    size_t b = r >> 12;
    xt[i] += x[(r + 1 + b) * DIM + d];
}

// ---------------- assemble ----------------
__global__ void __launch_bounds__(256) assemble_k(const float* __restrict__ x,
                                                  const float* __restrict__ xt,
                                                  const float* __restrict__ res_s,
                                                  float* __restrict__ out) {
    int r = blockIdx.x;
    int b = (r >= NSEQ) ? 1 : 0;
    int p = r - b * NSEQ;
    int tid = threadIdx.x;
    #pragma unroll
    for (int e = 0; e < 3; e++) {
        int d = tid + e * 256;
        float v;
        if (p == 0) {
            float acc = 0.f;
            #pragma unroll
            for (int t = 0; t < TT; t++)
                acc += res_s[((size_t)(b * TT + t) * SP) * DIM + d];
            v = x[(size_t)r * DIM + d] + acc * 0.25f;
        } else {
            int n = p - 1, s = n >> 2, t = n & 3;
            v = xt[((size_t)b * NTOK + n) * DIM + d]
              + res_s[((size_t)(b * TT + t) * SP + 1 + s) * DIM + d];
        }
        out[(size_t)r * DIM + d] = v;
    }
}

// ---------------- launch ----------------
extern "C" void kernel_launch(void* const* d_in, const int* in_sizes, int n_in,
                              void* d_out, int out_size) {
    (void)in_sizes; (void)n_in; (void)out_size;
    const float* x        = (const float*)d_in[0];
    const float* norm1_g  = (const float*)d_in[1];
    const float* norm1_b  = (const float*)d_in[2];
    const float* qkv_w    = (const float*)d_in[3];
    const float* proj_w   = (const float*)d_in[4];
    const float* proj_b   = (const float*)d_in[5];
    const float* wg_w     = (const float*)d_in[6];
    const float* wg_b     = (const float*)d_in[7];
    const float* tnorm1_g = (const float*)d_in[8];
    const float* tnorm1_b = (const float*)d_in[9];
    const float* tqkv_w   = (const float*)d_in[10];
    const float* tproj_w  = (const float*)d_in[11];
    const float* tproj_b  = (const float*)d_in[12];
    const float* tfc_w    = (const float*)d_in[13];
    const float* tfc_b    = (const float*)d_in[14];
    const float* norm2_g  = (const float*)d_in[15];
    const float* norm2_b  = (const float*)d_in[16];
    const float* fc1_w    = (const float*)d_in[17];
    const float* fc1_b    = (const float*)d_in[18];
    const float* fc2_w    = (const float*)d_in[19];
    const float* fc2_b    = (const float*)d_in[20];
    float* out = (float*)d_out;

    float *big, *tmp, *xt, *sc, *tab;
    cudaGetSymbolAddress((void**)&big, g_big);
    cudaGetSymbolAddress((void**)&tmp, g_tmp);
    cudaGetSymbolAddress((void**)&xt,  g_xt);
    cudaGetSymbolAddress((void**)&sc,  g_sc);
    cudaGetSymbolAddress((void**)&tab, g_tab);
    __nv_bfloat16 *wh, *wl, *lnh, *lnl, *ath, *atl, *tph, *tpl, *bgh, *bgl;
    cudaGetSymbolAddress((void**)&wh,  g_wh4);
    cudaGetSymbolAddress((void**)&wl,  g_wl4);
    cudaGetSymbolAddress((void**)&lnh, g_lnh4);
    cudaGetSymbolAddress((void**)&lnl, g_lnl4);
    cudaGetSymbolAddress((void**)&ath, g_ath4);
    cudaGetSymbolAddress((void**)&atl, g_atl4);
    cudaGetSymbolAddress((void**)&tph, g_tph4);
    cudaGetSymbolAddress((void**)&tpl, g_tpl4);
    cudaGetSymbolAddress((void**)&bgh, g_bgh4);
    cudaGetSymbolAddress((void**)&bgl, g_bgl4);

    cudaFuncSetAttribute(mma_gemm_k<false,false,false>, cudaFuncAttributeMaxDynamicSharedMemorySize, MM_SMEM);
    cudaFuncSetAttribute(mma_gemm_k<false,false,true>,  cudaFuncAttributeMaxDynamicSharedMemorySize, MM_SMEM);
    cudaFuncSetAttribute(mma_gemm_k<true,false,true>,   cudaFuncAttributeMaxDynamicSharedMemorySize, MM_SMEM);
    cudaFuncSetAttribute(mma_gemm_k<false,true,false>,  cudaFuncAttributeMaxDynamicSharedMemorySize, MM_SMEM);

    const long SPSP = (long)SP * SP;

    bias_tab_k<<<16, 256>>>(wg_w, wg_b, tab);
    // weight conversions
    cvt_k<<<(1769472 + 255) / 256, 256>>>(tqkv_w, wh + OFF_TQKV, wl + OFF_TQKV, 1769472);
    cvt_k<<<(589824 + 255) / 256, 256>>>(tproj_w, wh + OFF_TPROJ, wl + OFF_TPROJ, 589824);
    cvt_k<<<(589824 + 255) / 256, 256>>>(tfc_w, wh + OFF_TFC, wl + OFF_TFC, 589824);
    cvt_k<<<(1769472 + 255) / 256, 256>>>(qkv_w, wh + OFF_QKV, wl + OFF_QKV, 1769472);
    cvt_k<<<(589824 + 255) / 256, 256>>>(proj_w, wh + OFF_PROJ, wl + OFF_PROJ, 589824);
    cvt_k<<<(2359296 + 255) / 256, 256>>>(fc1_w, wh + OFF_FC1, wl + OFF_FC1, 2359296);
    cvt_k<<<(2359296 + 255) / 256, 256>>>(fc2_w, wh + OFF_FC2, wl + OFF_FC2, 2359296);

    // ---- temporal branch ----
    ln_k<0><<<MT, 256>>>(x, nullptr, tnorm1_g, tnorm1_b, lnh, lnl);
    mma_gemm_k<false,false,false><<<dim3(18, 64), 256, MM_SMEM>>>(
        lnh, lnl, wh + OFF_TQKV, wl + OFF_TQKV, nullptr, nullptr,
        big, nullptr, nullptr, MT, 3*DIM, DIM, 3*DIM);
    attn_temporal_k<<<(MT/4*HEADS)/4, 128>>>(big, ath, atl);
    mma_gemm_k<false,false,true><<<dim3(6, 64), 256, MM_SMEM>>>(
        ath, atl, wh + OFF_TPROJ, wl + OFF_TPROJ, tproj_b, nullptr,
        nullptr, tph, tpl, MT, DIM, DIM, DIM);
    mma_gemm_k<false,false,false><<<dim3(6, 64), 256, MM_SMEM>>>(
        tph, tpl, wh + OFF_TFC, wl + OFF_TFC, tfc_b, nullptr,
        xt, nullptr, nullptr, MT, DIM, DIM, DIM);
    add_x_k<<<(int)(((size_t)MT*DIM + 255)/256), 256>>>(xt, x);

    // ---- spatial branch ----
    ln_k<1><<<MS, 256>>>(x, xt, norm1_g, norm1_b, lnh, lnl);
    mma_gemm_k<false,false,false><<<dim3(18, 65), 256, MM_SMEM>>>(
        lnh, lnl, wh + OFF_QKV, wl + OFF_QKV, nullptr, nullptr,
        big, nullptr, nullptr, MS, 3*DIM, DIM, 3*DIM);
    gemm_k<128,128,16,8,8,false,2,false><<<dim3(9,9,NBH), 256>>>(
        big, big + DIM, tab, sc, nullptr, nullptr,
        SP, SP, HD, 3*DIM, 3*DIM, SP,
        (long)SP*3*DIM, 64L, (long)SP*3*DIM, 64L,
        (long)HEADS*SPSP, SPSP, 0.125f);
    softmax_k<<<NBH*SP, 256>>>(sc, SP);
    gemm_k<128,64,16,8,4,true,0,true><<<dim3(1,9,NBH), 256>>>(
        sc, big + 2*DIM, nullptr, nullptr, ath, atl,
        SP, HD, SP, SP, 3*DIM, DIM,
        (long)HEADS*SPSP, SPSP, (long)SP*3*DIM, 64L,
        (long)SP*DIM, 64L, 1.0f);
    mma_gemm_k<false,false,false><<<dim3(6, 65), 256, MM_SMEM>>>(
        ath, atl, wh + OFF_PROJ, wl + OFF_PROJ, proj_b, nullptr,
        tmp, nullptr, nullptr, MS, DIM, DIM, DIM);

    // ---- assemble xout into d_out ----
    assemble_k<<<MO, 256>>>(x, xt, tmp, out);

    // ---- MLP ----
    ln_k<2><<<MO, 256>>>(out, nullptr, norm2_g, norm2_b, lnh, lnl);
    mma_gemm_k<true,false,true><<<dim3(24, 65), 256, MM_SMEM>>>(
        lnh, lnl, wh + OFF_FC1, wl + OFF_FC1, fc1_b, nullptr,
        nullptr, bgh, bgl, MO, MLPH, DIM, MLPH);
    mma_gemm_k<false,true,false><<<dim3(6, 65), 256, MM_SMEM>>>(
        bgh, bgl, wh + OFF_FC2, wl + OFF_FC2, fc2_b, out,
        out, nullptr, nullptr, MO, DIM, MLPH, DIM);
}

// round 13
// speedup vs baseline: 2.9016x; 1.4075x over previous
#include <cuda_runtime.h>
#include <cuda_bf16.h>
#include <math.h>
#include <stdint.h>

// ---------------- problem constants ----------------
#define DIM    768
#define HEADS  12
#define HD     64
#define TT     4
#define NTOK   4096
#define NSEQ   4097
#define SP     1025
#define MLPH   3072
#define MT     8192
#define MS     8200
#define MO     8194
#define NBH    96
#define VTL_STRIDE 1032

// ---------------- scratch (static device; no allocations) ----------------
__device__ float g_big[(size_t)MO * MLPH];       // temporal qkv out (fp32)
__device__ float g_tmp[(size_t)MS * DIM];
__device__ float g_xt [(size_t)MT * DIM];
__device__ float g_tab[HEADS * 63 * 63];
// bf16 hi/lo planes (uint4 for 16B alignment)
__device__ uint4 g_wh4 [1253376], g_wl4 [1253376];   // weights
__device__ uint4 g_lnh4[787200],  g_lnl4[787200];    // layernorm out (MS x DIM)
__device__ uint4 g_ath4[787200],  g_atl4[787200];    // attention out (MS x DIM)
__device__ uint4 g_tph4[786432],  g_tpl4[786432];    // tproj out (MT x DIM)
__device__ uint4 g_bgh4[3146496], g_bgl4[3146496];   // spatial qkv planes / fc1 out
__device__ uint4 g_vth4[792832],  g_vtl4[792832];    // V transposed [bh*64+d][1032]

// weight plane offsets (elements)
#define OFF_TQKV 0
#define OFF_TPROJ 1769472
#define OFF_TFC  2359296
#define OFF_QKV  2949120
#define OFF_PROJ 4718592
#define OFF_FC1  5308416
#define OFF_FC2  7667712

// ---------------- helpers ----------------
__device__ __forceinline__ uint32_t smem_u32(const void* p) {
    uint32_t a;
    asm("{ .reg .u64 t; cvta.to.shared.u64 t, %1; cvt.u32.u64 %0, t; }" : "=r"(a) : "l"(p));
    return a;
}
__device__ __forceinline__ float warp_sum(float v) {
    #pragma unroll
    for (int o = 16; o; o >>= 1) v += __shfl_xor_sync(0xffffffffu, v, o);
    return v;
}
__device__ __forceinline__ float gelu_f(float x) {
    return 0.5f * x * (1.0f + erff(x * 0.70710678118654752440f));
}
__device__ __forceinline__ void split_bf16(float v, __nv_bfloat16& h, __nv_bfloat16& l) {
    h = __float2bfloat16(v);
    l = __float2bfloat16(v - __bfloat162float(h));
}
__device__ __forceinline__ void pack2(float a, float b, uint32_t& hi, uint32_t& lo) {
    __nv_bfloat16 ha, la, hb, lb;
    split_bf16(a, ha, la); split_bf16(b, hb, lb);
    hi = ((uint32_t)__bfloat16_as_ushort(hb) << 16) | __bfloat16_as_ushort(ha);
    lo = ((uint32_t)__bfloat16_as_ushort(lb) << 16) | __bfloat16_as_ushort(la);
}

// ---------------- weight fp32 -> bf16 hi/lo ----------------
__global__ void cvt_k(const float* __restrict__ src, __nv_bfloat16* __restrict__ h,
                      __nv_bfloat16* __restrict__ l, int n) {
    int i = blockIdx.x * 256 + threadIdx.x;
    if (i < n) {
        __nv_bfloat16 hh, ll;
        split_bf16(src[i], hh, ll);
        h[i] = hh; l[i] = ll;
    }
}

// ---------------- geometry bias table ----------------
__global__ void bias_tab_k(const float* __restrict__ wg_w,
                           const float* __restrict__ wg_b,
                           float* __restrict__ tab) {
    int idx = blockIdx.x * blockDim.x + threadIdx.x;
    if (idx >= 63 * 63) return;
    int di = idx / 63 - 31;
    int dj = idx % 63 - 31;
    const float wbox = 1.0f + 1.0f / 32.0f;
    float dx = logf(fmaxf(fabsf(((float)di / 32.0f) / wbox), 1e-3f));
    float dy = logf(fmaxf(fabsf(((float)dj / 32.0f) / wbox), 1e-3f));
    float sx[8], cx[8], sy[8], cy[8];
    #pragma unroll
    for (int k = 0; k < 8; k++) {
        float dm = exp10f(-3.0f * (float)k / 8.0f);
        sincosf(100.0f * dx * dm, &sx[k], &cx[k]);
        sincosf(100.0f * dy * dm, &sy[k], &cy[k]);
    }
    for (int h = 0; h < HEADS; h++) {
        const float* w = wg_w + h * 64;
        float acc = wg_b[h];
        #pragma unroll
        for (int k = 0; k < 8; k++) {
            acc += w[k] * sx[k];
            acc += w[8 + k] * sy[k];
            acc += w[32 + k] * cx[k];
            acc += w[40 + k] * cy[k];
        }
        #pragma unroll
        for (int k = 48; k < 64; k++) acc += w[k];
        tab[h * 3969 + idx] = logf(fmaxf(acc, 1e-6f));
    }
}

// ---------------- layernorm -> bf16 hi/lo planes ----------------
template <int MODE>
__global__ void __launch_bounds__(256) ln_k(const float* __restrict__ src0,
                                            const float* __restrict__ src1,
                                            const float* __restrict__ gam,
                                            const float* __restrict__ bet,
                                            __nv_bfloat16* __restrict__ oh,
                                            __nv_bfloat16* __restrict__ ol) {
    int r = blockIdx.x;
    const float* src;
    if (MODE == 0) {
        int b = r >> 12, n = r & 4095;
        src = src0 + ((size_t)b * NSEQ + 1 + n) * DIM;
    } else if (MODE == 1) {
        int bt = r / SP, p = r % SP;
        int b = bt >> 2, t = bt & 3;
        src = (p == 0) ? (src0 + (size_t)b * NSEQ * DIM)
                       : (src1 + ((size_t)b * NTOK + 4 * (p - 1) + t) * DIM);
    } else {
        src = src0 + (size_t)r * DIM;
    }
    int tid = threadIdx.x;
    float v[3], s = 0.f, ss = 0.f;
    #pragma unroll
    for (int e = 0; e < 3; e++) {
        float xv = src[tid + e * 256];
        v[e] = xv; s += xv; ss += xv * xv;
    }
    __shared__ float sh1[8], sh2[8], fin[2];
    float wsu = warp_sum(s), wss = warp_sum(ss);
    int wid = tid >> 5, lane = tid & 31;
    if (lane == 0) { sh1[wid] = wsu; sh2[wid] = wss; }
    __syncthreads();
    if (tid == 0) {
        float a = 0.f, b = 0.f;
        #pragma unroll
        for (int i = 0; i < 8; i++) { a += sh1[i]; b += sh2[i]; }
        fin[0] = a; fin[1] = b;
    }
    __syncthreads();
    float mean = fin[0] * (1.0f / DIM);
    float var  = fin[1] * (1.0f / DIM) - mean * mean;
    float rstd = rsqrtf(var + 1e-5f);
    #pragma unroll
    for (int e = 0; e < 3; e++) {
        int c = tid + e * 256;
        float y = (v[e] - mean) * rstd * gam[c] + bet[c];
        __nv_bfloat16 hh, ll;
        split_bf16(y, hh, ll);
        oh[(size_t)r * DIM + c] = hh;
        ol[(size_t)r * DIM + c] = ll;
    }
}

// ================= bf16x3 tensor-core GEMM via mma.sync =================
#define MM_SMEM 81920

__device__ __forceinline__ void mma_bf16(float* d, const uint32_t* a, const uint32_t* b) {
    asm volatile(
        "mma.sync.aligned.m16n8k16.row.col.f32.bf16.bf16.f32 "
        "{%0,%1,%2,%3}, {%4,%5,%6,%7}, {%8,%9}, {%0,%1,%2,%3};"
        : "+f"(d[0]), "+f"(d[1]), "+f"(d[2]), "+f"(d[3])
        : "r"(a[0]), "r"(a[1]), "r"(a[2]), "r"(a[3]), "r"(b[0]), "r"(b[1]));
}

__device__ __forceinline__ void fill_stage(
    char* smem, int stage,
    const __nv_bfloat16* __restrict__ Ah, const __nv_bfloat16* __restrict__ Al,
    const __nv_bfloat16* __restrict__ Bh, const __nv_bfloat16* __restrict__ Bl,
    int brow, int bcol, int M, int K, int kt) {
    uint32_t sb = smem_u32(smem) + (uint32_t)stage * 40960u;
    int tid = threadIdx.x;
    const __nv_bfloat16* planes[4] = {Ah, Al, Bh, Bl};
    #pragma unroll
    for (int p = 0; p < 4; p++) {
        int rbase = (p < 2) ? brow : bcol;
        #pragma unroll
        for (int q = 0; q < 2; q++) {
            int id = tid + q * 256;
            int row = id >> 2, ch = id & 3;
            int grow = rbase + row;
            bool ok = (p >= 2) || (grow < M);
            const __nv_bfloat16* src = planes[p] +
                ((size_t)(ok ? grow : 0) * K + kt * 32 + ch * 8);
            uint32_t dst = sb + (uint32_t)p * 10240u + (uint32_t)(row * 80 + ch * 16);
            int sz = ok ? 16 : 0;
            asm volatile("cp.async.cg.shared.global [%0], [%1], 16, %2;"
                         :: "r"(dst), "l"(src), "r"(sz));
        }
    }
}

template <bool GELU, bool RES, bool OUT16>
__global__ void __launch_bounds__(256) mma_gemm_k(
    const __nv_bfloat16* __restrict__ Ah, const __nv_bfloat16* __restrict__ Al,
    const __nv_bfloat16* __restrict__ Bh, const __nv_bfloat16* __restrict__ Bl,
    const float* __restrict__ bias, const float* __restrict__ resid,
    float* __restrict__ C, __nv_bfloat16* __restrict__ Ch, __nv_bfloat16* __restrict__ Cl,
    int M, int N, int K, int ldc) {
    extern __shared__ char smem[];
    const int tid = threadIdx.x, wid = tid >> 5, lane = tid & 31;
    const int wm = wid >> 2, wn = wid & 3;
    const int brow = blockIdx.y * 128, bcol = blockIdx.x * 128;
    const int KT = K >> 5;

    float acc[4][4][4];
    #pragma unroll
    for (int i = 0; i < 4; i++)
        #pragma unroll
        for (int j = 0; j < 4; j++)
            #pragma unroll
            for (int r = 0; r < 4; r++) acc[i][j][r] = 0.f;

    fill_stage(smem, 0, Ah, Al, Bh, Bl, brow, bcol, M, K, 0);
    asm volatile("cp.async.commit_group;");

    for (int kt = 0; kt < KT; kt++) {
        if (kt + 1 < KT) {
            fill_stage(smem, (kt + 1) & 1, Ah, Al, Bh, Bl, brow, bcol, M, K, kt + 1);
            asm volatile("cp.async.commit_group;");
            asm volatile("cp.async.wait_group 1;");
        } else {
            asm volatile("cp.async.wait_group 0;");
        }
        __syncthreads();

        char* sbuf = smem + (kt & 1) * 40960;
        const __nv_bfloat16* As_h = (const __nv_bfloat16*)sbuf;
        const __nv_bfloat16* As_l = (const __nv_bfloat16*)(sbuf + 10240);
        const __nv_bfloat16* Bs_h = (const __nv_bfloat16*)(sbuf + 20480);
        const __nv_bfloat16* Bs_l = (const __nv_bfloat16*)(sbuf + 30720);

        #pragma unroll
        for (int ks = 0; ks < 2; ks++) {
            int c = ks * 16 + (lane & 3) * 2;
            uint32_t ah[4][4], al[4][4], bh[4][2], bl[4][2];
            #pragma unroll
            for (int i = 0; i < 4; i++) {
                int r = wm * 64 + i * 16 + (lane >> 2);
                const __nv_bfloat16* ph = As_h + r * 40 + c;
                const __nv_bfloat16* pl = As_l + r * 40 + c;
                ah[i][0] = *(const uint32_t*)ph;
                ah[i][1] = *(const uint32_t*)(ph + 320);
                ah[i][2] = *(const uint32_t*)(ph + 8);
                ah[i][3] = *(const uint32_t*)(ph + 328);
                al[i][0] = *(const uint32_t*)pl;
                al[i][1] = *(const uint32_t*)(pl + 320);
                al[i][2] = *(const uint32_t*)(pl + 8);
                al[i][3] = *(const uint32_t*)(pl + 328);
            }
            #pragma unroll
            for (int j = 0; j < 4; j++) {
                int r = wn * 32 + j * 8 + (lane >> 2);
                const __nv_bfloat16* ph = Bs_h + r * 40 + c;
                const __nv_bfloat16* pl = Bs_l + r * 40 + c;
                bh[j][0] = *(const uint32_t*)ph;
                bh[j][1] = *(const uint32_t*)(ph + 8);
                bl[j][0] = *(const uint32_t*)pl;
                bl[j][1] = *(const uint32_t*)(pl + 8);
            }
            #pragma unroll
            for (int i = 0; i < 4; i++)
                #pragma unroll
                for (int j = 0; j < 4; j++) {
                    mma_bf16(acc[i][j], ah[i], bh[j]);
                    mma_bf16(acc[i][j], ah[i], bl[j]);
                    mma_bf16(acc[i][j], al[i], bh[j]);
                }
        }
        __syncthreads();
    }

    #pragma unroll
    for (int i = 0; i < 4; i++) {
        int r0 = brow + wm * 64 + i * 16 + (lane >> 2);
        int r1 = r0 + 8;
        #pragma unroll
        for (int j = 0; j < 4; j++) {
            int col = bcol + wn * 32 + j * 8 + (lane & 3) * 2;
            float b0 = bias ? __ldg(&bias[col]) : 0.f;
            float b1 = bias ? __ldg(&bias[col + 1]) : 0.f;
            #pragma unroll
            for (int half = 0; half < 2; half++) {
                int gr = half ? r1 : r0;
                if (gr >= M) continue;
                float v0 = acc[i][j][half * 2 + 0] + b0;
                float v1 = acc[i][j][half * 2 + 1] + b1;
                if (GELU) { v0 = gelu_f(v0); v1 = gelu_f(v1); }
                if (RES) {
                    v0 += resid[(size_t)gr * ldc + col];
                    v1 += resid[(size_t)gr * ldc + col + 1];
                }
                if (OUT16) {
                    __nv_bfloat16 h0, l0, h1, l1;
                    split_bf16(v0, h0, l0);
                    split_bf16(v1, h1, l1);
                    uint32_t hp = ((uint32_t)__bfloat16_as_ushort(h1) << 16) | __bfloat16_as_ushort(h0);
                    uint32_t lp = ((uint32_t)__bfloat16_as_ushort(l1) << 16) | __bfloat16_as_ushort(l0);
                    *(uint32_t*)(Ch + (size_t)gr * ldc + col) = hp;
                    *(uint32_t*)(Cl + (size_t)gr * ldc + col) = lp;
                } else {
                    *(float2*)(C + (size_t)gr * ldc + col) = make_float2(v0, v1);
                }
            }
        }
    }
}

// ---------------- V transpose: planes [row][dim] -> [bh*64+d][1032 keys] ----------------
__global__ void __launch_bounds__(256) vtrans_k(const __nv_bfloat16* __restrict__ vh,
                                                const __nv_bfloat16* __restrict__ vl,
                                                __nv_bfloat16* __restrict__ oth,
                                                __nv_bfloat16* __restrict__ otl) {
    __shared__ __nv_bfloat16 th[64][72], tl[64][72];
    int bh = blockIdx.y, pb = blockIdx.x;
    int bt = bh / HEADS, hh = bh % HEADS;
    const size_t ib = (size_t)bt * SP * (3 * DIM) + 2 * DIM + hh * HD;
    int tid = threadIdx.x;
    #pragma unroll
    for (int i = 0; i < 16; i++) {
        int idx = tid + i * 256;
        int pl_ = idx >> 6, d = idx & 63;
        int p = pb * 64 + pl_;
        __nv_bfloat16 a = __float2bfloat16(0.f), b = a;
        if (p < SP) {
            a = vh[ib + (size_t)p * (3 * DIM) + d];
            b = vl[ib + (size_t)p * (3 * DIM) + d];
        }
        th[d][pl_] = a; tl[d][pl_] = b;
    }
    __syncthreads();
    const size_t ob = (size_t)bh * HD * VTL_STRIDE + pb * 64;
    #pragma unroll
    for (int i = 0; i < 16; i++) {
        int idx = tid + i * 256;
        int d = idx >> 6, pl_ = idx & 63;
        int p = pb * 64 + pl_;
        if (p < VTL_STRIDE) {
            oth[ob + (size_t)d * VTL_STRIDE + pl_] = th[d][pl_];
            otl[ob + (size_t)d * VTL_STRIDE + pl_] = tl[d][pl_];
        }
    }
}

// ================= fused flash attention (spatial) =================
// CTA: 128 q-rows x full 1025-key loop, per (bt, head). bf16x3 throughout.
#define FL_SMEM 108544

__global__ void __launch_bounds__(256) flash_k(
    const __nv_bfloat16* __restrict__ qkh, const __nv_bfloat16* __restrict__ qkl,
    const __nv_bfloat16* __restrict__ vth, const __nv_bfloat16* __restrict__ vtl,
    const float* __restrict__ tab,
    __nv_bfloat16* __restrict__ ooh, __nv_bfloat16* __restrict__ ool) {
    extern __shared__ char sm[];
    const int tid = threadIdx.x, wid = tid >> 5, lane = tid & 31;
    const int qb = blockIdx.x, bh = blockIdx.y;
    const int bt = bh / HEADS, h = bh % HEADS;
    const size_t sbase = (size_t)bt * SP * (3 * DIM) + h * HD;
    const size_t vtbase = (size_t)bh * HD * VTL_STRIDE;
    uint32_t sb = smem_u32(sm);
    const uint32_t QH = 0u, QL = 18432u, KH = 36864u, KL = 55296u, VH = 73728u, VL = 91136u;
    const __nv_bfloat16* smQH = (const __nv_bfloat16*)(sm + QH);
    const __nv_bfloat16* smQL = (const __nv_bfloat16*)(sm + QL);
    const __nv_bfloat16* smKH = (const __nv_bfloat16*)(sm + KH);
    const __nv_bfloat16* smKL = (const __nv_bfloat16*)(sm + KL);
    const __nv_bfloat16* smVH = (const __nv_bfloat16*)(sm + VH);
    const __nv_bfloat16* smVL = (const __nv_bfloat16*)(sm + VL);

    // Q tile (stride 72 elems, conflict-free frag loads)
    #pragma unroll
    for (int i = 0; i < 4; i++) {
        int idx = tid + i * 256, r = idx >> 3, c = idx & 7;
        int p = qb * 128 + r;
        int sz = (p < SP) ? 16 : 0;
        uint32_t dof = (uint32_t)(r * 144 + c * 16);
        asm volatile("cp.async.cg.shared.global [%0], [%1], 16, %2;"
            :: "r"(sb + QH + dof), "l"(qkh + sbase + (size_t)p * (3 * DIM) + c * 8), "r"(sz));
        asm volatile("cp.async.cg.shared.global [%0], [%1], 16, %2;"
            :: "r"(sb + QL + dof), "l"(qkl + sbase + (size_t)p * (3 * DIM) + c * 8), "r"(sz));
    }
    asm volatile("cp.async.commit_group;");

    const int rA = wid * 16 + (lane >> 2);
    const int pA = qb * 128 + rA, pB = pA + 8;
    float mA = -1e30f, mB = -1e30f, lA = 0.f, lB = 0.f;
    float O[8][4];
    #pragma unroll
    for (int f = 0; f < 8; f++) { O[f][0] = 0.f; O[f][1] = 0.f; O[f][2] = 0.f; O[f][3] = 0.f; }

    for (int kb = 0; kb < 9; kb++) {
        __syncthreads();
        #pragma unroll
        for (int i = 0; i < 4; i++) {
            int idx = tid + i * 256, r = idx >> 3, c = idx & 7;
            int p = kb * 128 + r;
            int sz = (p < SP) ? 16 : 0;
            uint32_t dof = (uint32_t)(r * 144 + c * 16);
            asm volatile("cp.async.cg.shared.global [%0], [%1], 16, %2;"
                :: "r"(sb + KH + dof), "l"(qkh + sbase + DIM + (size_t)p * (3 * DIM) + c * 8), "r"(sz));
            asm volatile("cp.async.cg.shared.global [%0], [%1], 16, %2;"
                :: "r"(sb + KL + dof), "l"(qkl + sbase + DIM + (size_t)p * (3 * DIM) + c * 8), "r"(sz));
        }
        #pragma unroll
        for (int i = 0; i < 4; i++) {
            int idx = tid + i * 256, d = idx >> 4, kc = idx & 15;
            int k0 = kb * 128 + kc * 8;
            int sz = (k0 < VTL_STRIDE) ? 16 : 0;
            uint32_t dof = (uint32_t)(d * 272 + kc * 16);
            asm volatile("cp.async.cg.shared.global [%0], [%1], 16, %2;"
                :: "r"(sb + VH + dof), "l"(vth + vtbase + (size_t)d * VTL_STRIDE + k0), "r"(sz));
            asm volatile("cp.async.cg.shared.global [%0], [%1], 16, %2;"
                :: "r"(sb + VL + dof), "l"(vtl + vtbase + (size_t)d * VTL_STRIDE + k0), "r"(sz));
        }
        asm volatile("cp.async.commit_group;");
        asm volatile("cp.async.wait_group 0;");
        __syncthreads();

        // S = Q K^T (bf16x3)
        float S[16][4];
        #pragma unroll
        for (int f = 0; f < 16; f++) { S[f][0] = 0.f; S[f][1] = 0.f; S[f][2] = 0.f; S[f][3] = 0.f; }
        #pragma unroll
        for (int ks = 0; ks < 4; ks++) {
            int c = ks * 16 + (lane & 3) * 2;
            const __nv_bfloat16* qh_p = smQH + rA * 72 + c;
            const __nv_bfloat16* ql_p = smQL + rA * 72 + c;
            uint32_t ah[4], al[4];
            ah[0] = *(const uint32_t*)qh_p;
            ah[1] = *(const uint32_t*)(qh_p + 8 * 72);
            ah[2] = *(const uint32_t*)(qh_p + 8);
            ah[3] = *(const uint32_t*)(qh_p + 8 * 72 + 8);
            al[0] = *(const uint32_t*)ql_p;
            al[1] = *(const uint32_t*)(ql_p + 8 * 72);
            al[2] = *(const uint32_t*)(ql_p + 8);
            al[3] = *(const uint32_t*)(ql_p + 8 * 72 + 8);
            #pragma unroll
            for (int f = 0; f < 16; f++) {
                int kr = f * 8 + (lane >> 2);
                const __nv_bfloat16* kh_p = smKH + kr * 72 + c;
                const __nv_bfloat16* kl_p = smKL + kr * 72 + c;
                uint32_t bhh[2] = { *(const uint32_t*)kh_p, *(const uint32_t*)(kh_p + 8) };
                uint32_t bll[2] = { *(const uint32_t*)kl_p, *(const uint32_t*)(kl_p + 8) };
                mma_bf16(S[f], ah, bhh);
                mma_bf16(S[f], ah, bll);
                mma_bf16(S[f], al, bhh);
            }
        }

        // scale + geometry bias + mask
        float bmA = -1e30f, bmB = -1e30f;
        #pragma unroll
        for (int f = 0; f < 16; f++) {
            int col0 = kb * 128 + f * 8 + (lane & 3) * 2;
            #pragma unroll
            for (int e = 0; e < 4; e++) {
                int pk = col0 + (e & 1);
                int pq = (e < 2) ? pA : pB;
                float s = S[f][e] * 0.125f;
                if (pk >= SP || pq >= SP) {
                    s = -1e30f;
                } else if (pq > 0 && pk > 0) {
                    int qi = pq - 1, kj = pk - 1;
                    s += __ldg(&tab[h * 3969 + ((qi >> 5) - (kj >> 5) + 31) * 63
                                    + ((qi & 31) - (kj & 31) + 31)]);
                }
                S[f][e] = s;
            }
            bmA = fmaxf(bmA, fmaxf(S[f][0], S[f][1]));
            bmB = fmaxf(bmB, fmaxf(S[f][2], S[f][3]));
        }
        bmA = fmaxf(bmA, __shfl_xor_sync(0xffffffffu, bmA, 1));
        bmA = fmaxf(bmA, __shfl_xor_sync(0xffffffffu, bmA, 2));
        bmB = fmaxf(bmB, __shfl_xor_sync(0xffffffffu, bmB, 1));
        bmB = fmaxf(bmB, __shfl_xor_sync(0xffffffffu, bmB, 2));
        float mnA = fmaxf(mA, bmA), mnB = fmaxf(mB, bmB);
        float scA = __expf(mA - mnA), scB = __expf(mB - mnB);
        mA = mnA; mB = mnB;
        lA *= scA; lB *= scB;
        #pragma unroll
        for (int f = 0; f < 8; f++) {
            O[f][0] *= scA; O[f][1] *= scA; O[f][2] *= scB; O[f][3] *= scB;
        }

        // P = exp(S - m), split hi/lo, PV mma (C-frag -> A-frag register repack)
        float sumA = 0.f, sumB = 0.f;
        #pragma unroll
        for (int kv = 0; kv < 8; kv++) {
            float p0 = __expf(S[2 * kv][0] - mnA),     p1 = __expf(S[2 * kv][1] - mnA);
            float p2 = __expf(S[2 * kv][2] - mnB),     p3 = __expf(S[2 * kv][3] - mnB);
            float p4 = __expf(S[2 * kv + 1][0] - mnA), p5 = __expf(S[2 * kv + 1][1] - mnA);
            float p6 = __expf(S[2 * kv + 1][2] - mnB), p7 = __expf(S[2 * kv + 1][3] - mnB);
            sumA += p0 + p1 + p4 + p5;
            sumB += p2 + p3 + p6 + p7;
            uint32_t ah[4], al[4];
            pack2(p0, p1, ah[0], al[0]);
            pack2(p2, p3, ah[1], al[1]);
            pack2(p4, p5, ah[2], al[2]);
            pack2(p6, p7, ah[3], al[3]);
            int kcc = kv * 16 + (lane & 3) * 2;
            #pragma unroll
            for (int fn = 0; fn < 8; fn++) {
                int nr = fn * 8 + (lane >> 2);
                const __nv_bfloat16* vh_p = smVH + nr * 136 + kcc;
                const __nv_bfloat16* vl_p = smVL + nr * 136 + kcc;
                uint32_t vbh[2] = { *(const uint32_t*)vh_p, *(const uint32_t*)(vh_p + 8) };
                uint32_t vbl[2] = { *(const uint32_t*)vl_p, *(const uint32_t*)(vl_p + 8) };
                mma_bf16(O[fn], ah, vbh);
                mma_bf16(O[fn], ah, vbl);
                mma_bf16(O[fn], al, vbh);
            }
        }
        sumA += __shfl_xor_sync(0xffffffffu, sumA, 1);
        sumA += __shfl_xor_sync(0xffffffffu, sumA, 2);
        sumB += __shfl_xor_sync(0xffffffffu, sumB, 1);
        sumB += __shfl_xor_sync(0xffffffffu, sumB, 2);
        lA += sumA; lB += sumB;
    }

    // epilogue: O /= l, write bf16 hi/lo planes
    float iA = 1.f / lA, iB = 1.f / lB;
    #pragma unroll
    for (int fn = 0; fn < 8; fn++) {
        int col = h * HD + fn * 8 + (lane & 3) * 2;
        if (pA < SP) {
            uint32_t hp, lp;
            pack2(O[fn][0] * iA, O[fn][1] * iA, hp, lp);
            *(uint32_t*)(ooh + ((size_t)bt * SP + pA) * DIM + col) = hp;
            *(uint32_t*)(ool + ((size_t)bt * SP + pA) * DIM + col) = lp;
        }
        if (pB < SP) {
            uint32_t hp, lp;
            pack2(O[fn][2] * iB, O[fn][3] * iB, hp, lp);
            *(uint32_t*)(ooh + ((size_t)bt * SP + pB) * DIM + col) = hp;
            *(uint32_t*)(ool + ((size_t)bt * SP + pB) * DIM + col) = lp;
        }
    }
}

// ---------------- temporal attention (writes bf16 hi/lo planes) ----------------
__global__ void __launch_bounds__(128) attn_temporal_k(const float* __restrict__ qkv,
                                                       __nv_bfloat16* __restrict__ oh,
                                                       __nv_bfloat16* __restrict__ ol) {
    __shared__ float sh[4][3][4][68];
    __shared__ float shp[4][4][4];
    int warp = threadIdx.x >> 5, lane = threadIdx.x & 31;
    int gid = blockIdx.x * 4 + warp;
    int seq = gid / HEADS, h = gid % HEADS;
    const float* base = qkv + (size_t)seq * 4 * (3 * DIM) + h * HD;
    #pragma unroll
    for (int i = 0; i < 4; i++)
        #pragma unroll
        for (int j = 0; j < 3; j++) {
            sh[warp][j][i][lane]      = base[(size_t)i * (3 * DIM) + j * DIM + lane];
            sh[warp][j][i][lane + 32] = base[(size_t)i * (3 * DIM) + j * DIM + lane + 32];
        }
    __syncwarp();
    if (lane < 16) {
        int i = lane >> 2, j = lane & 3;
        float s = 0.f;
        #pragma unroll
        for (int d = 0; d < 64; d++) s += sh[warp][0][i][d] * sh[warp][1][j][d];
        s *= 0.125f;
        float m = s;
        m = fmaxf(m, __shfl_xor_sync(0x0000ffffu, m, 1));
        m = fmaxf(m, __shfl_xor_sync(0x0000ffffu, m, 2));
        float e = expf(s - m);
        float t = e;
        t += __shfl_xor_sync(0x0000ffffu, t, 1);
        t += __shfl_xor_sync(0x0000ffffu, t, 2);
        shp[warp][i][j] = e / t;
    }
    __syncwarp();
    #pragma unroll
    for (int i = 0; i < 4; i++) {
        float o0 = 0.f, o1 = 0.f;
        #pragma unroll
        for (int j = 0; j < 4; j++) {
            float p = shp[warp][i][j];
            o0 += p * sh[warp][2][j][lane];
            o1 += p * sh[warp][2][j][lane + 32];
        }
        size_t base_o = ((size_t)seq * 4 + i) * DIM + h * HD;
        __nv_bfloat16 hh, ll;
        split_bf16(o0, hh, ll);
        oh[base_o + lane] = hh; ol[base_o + lane] = ll;
        split_bf16(o1, hh, ll);
        oh[base_o + lane + 32] = hh; ol[base_o + lane + 32] = ll;
    }
}

// ---------------- xt += x[:,1:] ----------------
__global__ void add_x_k(float* __restrict__ xt, const float* __restrict__ x) {
    size_t i = (size_t)blockIdx.x * blockDim.x + threadIdx.x;
    if (i >= (size_t)MT * DIM) return;
    size_t r = i / DIM, d = i % DIM;
    size_t b = r >> 12;
    xt[i] += x[(r + 1 + b) * DIM + d];
}

// ---------------- assemble ----------------
__global__ void __launch_bounds__(256) assemble_k(const float* __restrict__ x,
                                                  const float* __restrict__ xt,
                                                  const float* __restrict__ res_s,
                                                  float* __restrict__ out) {
    int r = blockIdx.x;
    int b = (r >= NSEQ) ? 1 : 0;
    int p = r - b * NSEQ;
    int tid = threadIdx.x;
    #pragma unroll
    for (int e = 0; e < 3; e++) {
        int d = tid + e * 256;
        float v;
        if (p == 0) {
            float acc = 0.f;
            #pragma unroll
            for (int t = 0; t < TT; t++)
                acc += res_s[((size_t)(b * TT + t) * SP) * DIM + d];
            v = x[(size_t)r * DIM + d] + acc * 0.25f;
        } else {
            int n = p - 1, s = n >> 2, t = n & 3;
            v = xt[((size_t)b * NTOK + n) * DIM + d]
              + res_s[((size_t)(b * TT + t) * SP + 1 + s) * DIM + d];
        }
        out[(size_t)r * DIM + d] = v;
    }
}

// ---------------- launch ----------------
extern "C" void kernel_launch(void* const* d_in, const int* in_sizes, int n_in,
                              void* d_out, int out_size) {
    (void)in_sizes; (void)n_in; (void)out_size;
    const float* x        = (const float*)d_in[0];
    const float* norm1_g  = (const float*)d_in[1];
    const float* norm1_b  = (const float*)d_in[2];
    const float* qkv_w    = (const float*)d_in[3];
    const float* proj_w   = (const float*)d_in[4];
    const float* proj_b   = (const float*)d_in[5];
    const float* wg_w     = (const float*)d_in[6];
    const float* wg_b     = (const float*)d_in[7];
    const float* tnorm1_g = (const float*)d_in[8];
    const float* tnorm1_b = (const float*)d_in[9];
    const float* tqkv_w   = (const float*)d_in[10];
    const float* tproj_w  = (const float*)d_in[11];
    const float* tproj_b  = (const float*)d_in[12];
    const float* tfc_w    = (const float*)d_in[13];
    const float* tfc_b    = (const float*)d_in[14];
    const float* norm2_g  = (const float*)d_in[15];
    const float* norm2_b  = (const float*)d_in[16];
    const float* fc1_w    = (const float*)d_in[17];
    const float* fc1_b    = (const float*)d_in[18];
    const float* fc2_w    = (const float*)d_in[19];
    const float* fc2_b    = (const float*)d_in[20];
    float* out = (float*)d_out;

    float *big, *tmp, *xt, *tab;
    cudaGetSymbolAddress((void**)&big, g_big);
    cudaGetSymbolAddress((void**)&tmp, g_tmp);
    cudaGetSymbolAddress((void**)&xt,  g_xt);
    cudaGetSymbolAddress((void**)&tab, g_tab);
    __nv_bfloat16 *wh, *wl, *lnh, *lnl, *ath, *atl, *tph, *tpl, *bgh, *bgl, *vth, *vtl;
    cudaGetSymbolAddress((void**)&wh,  g_wh4);
    cudaGetSymbolAddress((void**)&wl,  g_wl4);
    cudaGetSymbolAddress((void**)&lnh, g_lnh4);
    cudaGetSymbolAddress((void**)&lnl, g_lnl4);
    cudaGetSymbolAddress((void**)&ath, g_ath4);
    cudaGetSymbolAddress((void**)&atl, g_atl4);
    cudaGetSymbolAddress((void**)&tph, g_tph4);
    cudaGetSymbolAddress((void**)&tpl, g_tpl4);
    cudaGetSymbolAddress((void**)&bgh, g_bgh4);
    cudaGetSymbolAddress((void**)&bgl, g_bgl4);
    cudaGetSymbolAddress((void**)&vth, g_vth4);
    cudaGetSymbolAddress((void**)&vtl, g_vtl4);

    cudaFuncSetAttribute(mma_gemm_k<false,false,false>, cudaFuncAttributeMaxDynamicSharedMemorySize, MM_SMEM);
    cudaFuncSetAttribute(mma_gemm_k<false,false,true>,  cudaFuncAttributeMaxDynamicSharedMemorySize, MM_SMEM);
    cudaFuncSetAttribute(mma_gemm_k<true,false,true>,   cudaFuncAttributeMaxDynamicSharedMemorySize, MM_SMEM);
    cudaFuncSetAttribute(mma_gemm_k<false,true,false>,  cudaFuncAttributeMaxDynamicSharedMemorySize, MM_SMEM);
    cudaFuncSetAttribute(flash_k, cudaFuncAttributeMaxDynamicSharedMemorySize, FL_SMEM);

    bias_tab_k<<<16, 256>>>(wg_w, wg_b, tab);
    cvt_k<<<(1769472 + 255) / 256, 256>>>(tqkv_w, wh + OFF_TQKV, wl + OFF_TQKV, 1769472);
    cvt_k<<<(589824 + 255) / 256, 256>>>(tproj_w, wh + OFF_TPROJ, wl + OFF_TPROJ, 589824);
    cvt_k<<<(589824 + 255) / 256, 256>>>(tfc_w, wh + OFF_TFC, wl + OFF_TFC, 589824);
    cvt_k<<<(1769472 + 255) / 256, 256>>>(qkv_w, wh + OFF_QKV, wl + OFF_QKV, 1769472);
    cvt_k<<<(589824 + 255) / 256, 256>>>(proj_w, wh + OFF_PROJ, wl + OFF_PROJ, 589824);
    cvt_k<<<(2359296 + 255) / 256, 256>>>(fc1_w, wh + OFF_FC1, wl + OFF_FC1, 2359296);
    cvt_k<<<(2359296 + 255) / 256, 256>>>(fc2_w, wh + OFF_FC2, wl + OFF_FC2, 2359296);

    // ---- temporal branch ----
    ln_k<0><<<MT, 256>>>(x, nullptr, tnorm1_g, tnorm1_b, lnh, lnl);
    mma_gemm_k<false,false,false><<<dim3(18, 64), 256, MM_SMEM>>>(
        lnh, lnl, wh + OFF_TQKV, wl + OFF_TQKV, nullptr, nullptr,
        big, nullptr, nullptr, MT, 3*DIM, DIM, 3*DIM);
    attn_temporal_k<<<(MT/4*HEADS)/4, 128>>>(big, ath, atl);
    mma_gemm_k<false,false,true><<<dim3(6, 64), 256, MM_SMEM>>>(
        ath, atl, wh + OFF_TPROJ, wl + OFF_TPROJ, tproj_b, nullptr,
        nullptr, tph, tpl, MT, DIM, DIM, DIM);
    mma_gemm_k<false,false,false><<<dim3(6, 64), 256, MM_SMEM>>>(
        tph, tpl, wh + OFF_TFC, wl + OFF_TFC, tfc_b, nullptr,
        xt, nullptr, nullptr, MT, DIM, DIM, DIM);
    add_x_k<<<(int)(((size_t)MT*DIM + 255)/256), 256>>>(xt, x);

    // ---- spatial branch ----
    ln_k<1><<<MS, 256>>>(x, xt, norm1_g, norm1_b, lnh, lnl);
    // qkv -> bf16 planes (bgh/bgl), ldc = 2304
    mma_gemm_k<false,false,true><<<dim3(18, 65), 256, MM_SMEM>>>(
        lnh, lnl, wh + OFF_QKV, wl + OFF_QKV, nullptr, nullptr,
        nullptr, bgh, bgl, MS, 3*DIM, DIM, 3*DIM);
    vtrans_k<<<dim3(17, NBH), 256>>>(bgh, bgl, vth, vtl);
    flash_k<<<dim3(9, NBH), 256, FL_SMEM>>>(bgh, bgl, vth, vtl, tab, ath, atl);
    mma_gemm_k<false,false,false><<<dim3(6, 65), 256, MM_SMEM>>>(
        ath, atl, wh + OFF_PROJ, wl + OFF_PROJ, proj_b, nullptr,
        tmp, nullptr, nullptr, MS, DIM, DIM, DIM);

    // ---- assemble xout into d_out ----
    assemble_k<<<MO, 256>>>(x, xt, tmp, out);

    // ---- MLP ----
    ln_k<2><<<MO, 256>>>(out, nullptr, norm2_g, norm2_b, lnh, lnl);
    mma_gemm_k<true,false,true><<<dim3(24, 65), 256, MM_SMEM>>>(
        lnh, lnl, wh + OFF_FC1, wl + OFF_FC1, fc1_b, nullptr,
        nullptr, bgh, bgl, MO, MLPH, DIM, MLPH);
    mma_gemm_k<false,true,false><<<dim3(6, 65), 256, MM_SMEM>>>(
        bgh, bgl, wh + OFF_FC2, wl + OFF_FC2, fc2_b, out,
        out, nullptr, nullptr, MO, DIM, MLPH, DIM);
}